// round 14
// baseline (speedup 1.0000x reference)
#include <cuda_runtime.h>
#include <cuda_bf16.h>
#include <cstdint>
#include <math.h>

#define BB 32
#define NN 4096
#define DD 256
#define SS 16
#define KK 8
#define HH 128
#define NCHUNK 256
#define NBLK (NN / NCHUNK)      /* 16 chunks per batch */
#define PART (KK * SS + KK)     /* 136 partials per chunk */
#define NPROJ ((BB * NN) / 64)  /* 2048 projection blocks */
#define NTOT (NPROJ + BB)

// ---------------- device scratch ----------------
__device__ __align__(16) float g_k[BB * NN * SS];
__device__ __align__(16) float g_v[BB * NN * SS];
__device__ __align__(16) float g_slots[BB * KK * SS];
__device__ __align__(16) float g_q[BB * KK * SS];
__device__ __align__(16) float g_partial[BB * NBLK * PART];
__device__ __align__(16) float g_denom[BB * KK];

// ---------------- helpers ----------------
typedef unsigned long long ull;
__device__ __forceinline__ ull ffma2(ull a, ull b, ull c) {
    ull d;
    asm("fma.rn.f32x2 %0, %1, %2, %3;" : "=l"(d) : "l"(a), "l"(b), "l"(c));
    return d;
}
__device__ __forceinline__ float ull_lo(ull u) {
    return __uint_as_float((unsigned int)(u & 0xffffffffull));
}
__device__ __forceinline__ float ull_hi(ull u) {
    return __uint_as_float((unsigned int)(u >> 32));
}

__device__ __forceinline__ void mma16816(float& c0, float& c1, float& c2,
                                         float& c3, uint32_t a0, uint32_t a1,
                                         uint32_t a2, uint32_t a3, uint32_t b0,
                                         uint32_t b1) {
    asm volatile(
        "mma.sync.aligned.m16n8k16.row.col.f32.bf16.bf16.f32 "
        "{%0,%1,%2,%3}, {%4,%5,%6,%7}, {%8,%9}, {%0,%1,%2,%3};"
        : "+f"(c0), "+f"(c1), "+f"(c2), "+f"(c3)
        : "r"(a0), "r"(a1), "r"(a2), "r"(a3), "r"(b0), "r"(b1));
}
__device__ __forceinline__ void ldm4(uint32_t& r0, uint32_t& r1, uint32_t& r2,
                                     uint32_t& r3, uint32_t addr) {
    asm volatile(
        "ldmatrix.sync.aligned.m8n8.x4.shared.b16 {%0,%1,%2,%3}, [%4];"
        : "=r"(r0), "=r"(r1), "=r"(r2), "=r"(r3) : "r"(addr));
}
__device__ __forceinline__ ull pack_hi_lo(float a, float b, float c, float d,
                                          ull& lo_out) {
    __nv_bfloat162 h0 = __floats2bfloat162_rn(a, b);
    __nv_bfloat162 h1 = __floats2bfloat162_rn(c, d);
    __nv_bfloat162 l0 = __floats2bfloat162_rn(a - __low2float(h0), b - __high2float(h0));
    __nv_bfloat162 l1 = __floats2bfloat162_rn(c - __low2float(h1), d - __high2float(h1));
    lo_out = ((ull)(*(uint32_t*)&l1) << 32) | (*(uint32_t*)&l0);
    return ((ull)(*(uint32_t*)&h1) << 32) | (*(uint32_t*)&h0);
}
__device__ __forceinline__ uint32_t pack2(float a, float b, uint32_t& lo) {
    __nv_bfloat162 h = __floats2bfloat162_rn(a, b);
    __nv_bfloat162 l = __floats2bfloat162_rn(a - __low2float(h), b - __high2float(h));
    lo = *(uint32_t*)&l;
    return *(uint32_t*)&h;
}

// ---------------- Kernel A: single-pass bf16 HMMA projection, epilogue LN ---
// k = rs*(x@W') + (e - mu*rs*c),  W' = lnw (.) Wk,  c = sum_d W', e = sum_d lnb*Wk
// 64 rows/CTA, 256 threads, K in 4 quarters of 64. Row stride 144 B.
#define RSTR 144
#define A_HI 0
#define A_LO (64 * RSTR)                 /* 9216 */
#define B_HI (2 * 64 * RSTR)             /* 18432 */
#define B_LO (B_HI + 32 * RSTR)          /* 23040 */
#define MURS (B_LO + 32 * RSTR)          /* 27648: 64 x float2 */
#define CE_C (MURS + 512)                /* 28160: 32 floats */
#define CE_E (CE_C + 128)                /* 28288: 32 floats */
#define SMEM_LN (CE_E + 128)             /* 28416 */

__global__ void __launch_bounds__(256, 5) ln_proj_tc(
    const float* __restrict__ x, const float* __restrict__ lnw,
    const float* __restrict__ lnb, const float* __restrict__ wk,
    const float* __restrict__ wvm, const float* __restrict__ init_slots,
    const float* __restrict__ ln_s_w, const float* __restrict__ ln_s_b,
    const float* __restrict__ wq) {
    extern __shared__ char smem[];
    int tid = threadIdx.x, wid = tid >> 5, lane = tid & 31;
    int bx = blockIdx.x;

    // ---- fused q_init blocks ----
    if (bx >= NPROJ) {
        float* smq = (float*)smem;
        int b = bx - NPROJ;
        if (tid < 128) {
            int s = tid & 15;
            float v = init_slots[b * 128 + tid];
            float sum = v, sq = v * v;
#pragma unroll
            for (int o = 8; o; o >>= 1) {
                sum += __shfl_xor_sync(0xffffffffu, sum, o, 16);
                sq += __shfl_xor_sync(0xffffffffu, sq, o, 16);
            }
            float mu = sum * (1.f / SS);
            float rs = rsqrtf(sq * (1.f / SS) - mu * mu + 1e-5f);
            smq[tid] = (v - mu) * rs * ln_s_w[s] + ln_s_b[s];
        }
        __syncthreads();
        if (tid < 128) {
            int k = tid >> 4, t = tid & 15;
            float a = 0.f;
#pragma unroll
            for (int ss = 0; ss < SS; ss++) a += smq[k * SS + ss] * wq[t * SS + ss];
            g_q[b * 128 + tid] = a * 0.25f;
        }
        return;
    }

    uint32_t sb = (uint32_t)__cvta_generic_to_shared(smem);
    int rtile = wid >> 1, chalf = wid & 1;
    int brow = tid >> 3, bseg = tid & 7;
    const float* wsrc_base =
        ((brow < SS) ? (wk + brow * DD) : (wvm + (brow - SS) * DD)) + bseg * 8;

    float s_acc[8], q_acc[8];
#pragma unroll
    for (int rr = 0; rr < 8; rr++) { s_acc[rr] = 0.f; q_acc[rr] = 0.f; }
    float c_acc = 0.f, e_acc = 0.f;
    float acc[2][4];
#pragma unroll
    for (int t = 0; t < 2; t++)
#pragma unroll
        for (int j = 0; j < 4; j++) acc[t][j] = 0.f;

#pragma unroll 1
    for (int h = 0; h < 4; h++) {
        __syncthreads();  // previous quarter's MMA reads done

        // ---- stage B: W' = lnw .* W row-slice, bf16 split; accumulate c,e
        {
            const float* src = wsrc_base + h * 64;
            char* bh = smem + B_HI + brow * RSTR + bseg * 16;
            char* bl = smem + B_LO + brow * RSTR + bseg * 16;
#pragma unroll
            for (int i = 0; i < 2; i++) {
                float4 f = *(const float4*)(src + i * 4);
                float4 w = *(const float4*)(lnw + h * 64 + bseg * 8 + i * 4);
                float4 b = *(const float4*)(lnb + h * 64 + bseg * 8 + i * 4);
                float px = f.x * w.x, py = f.y * w.y, pz = f.z * w.z, pw = f.w * w.w;
                c_acc += (px + py) + (pz + pw);
                e_acc += (f.x * b.x + f.y * b.y) + (f.z * b.z + f.w * b.w);
                ull lo;
                ull hi = pack_hi_lo(px, py, pz, pw, lo);
                *(ull*)(bh + i * 8) = hi;
                *(ull*)(bl + i * 8) = lo;
            }
        }

        // ---- stage A: raw x quarter, bf16 split; accumulate row sums
        {
            const float2* xr =
                (const float2*)(x + ((size_t)bx * 64 + wid * 8) * DD + h * 64);
#pragma unroll
            for (int rr = 0; rr < 8; rr++) {
                float2 a = xr[rr * 128 + lane];
                s_acc[rr] += a.x + a.y;
                q_acc[rr] += a.x * a.x + a.y * a.y;
                uint32_t lo;
                uint32_t hi = pack2(a.x, a.y, lo);
                char* ah = smem + A_HI + (wid * 8 + rr) * RSTR + 4 * lane;
                *(uint32_t*)ah = hi;
                *(uint32_t*)(ah + (A_LO - A_HI)) = lo;
            }
        }
        __syncthreads();

        // ---- MMA: 4 k-steps, ldmatrix fragments
        {
            int tr = lane & 7, sel = lane >> 3;
            uint32_t a_addr = sb + A_HI +
                              (uint32_t)(rtile * 16 + tr + ((sel & 1) << 3)) * RSTR +
                              ((sel >> 1) << 4);
            uint32_t b_addr = sb + B_HI +
                              (uint32_t)(chalf * 16 + tr + ((sel >> 1) << 3)) * RSTR +
                              ((sel & 1) << 4);
#pragma unroll
            for (int ks = 0; ks < 4; ks++) {
                uint32_t ah0, ah1, ah2, ah3, al0, al1, al2, al3;
                uint32_t bh0, bh1, bh2, bh3, bl0, bl1, bl2, bl3;
                ldm4(ah0, ah1, ah2, ah3, a_addr + ks * 32);
                ldm4(al0, al1, al2, al3, a_addr + (A_LO - A_HI) + ks * 32);
                ldm4(bh0, bh1, bh2, bh3, b_addr + ks * 32);
                ldm4(bl0, bl1, bl2, bl3, b_addr + (B_LO - B_HI) + ks * 32);
                mma16816(acc[0][0], acc[0][1], acc[0][2], acc[0][3],
                         ah0, ah1, ah2, ah3, bh0, bh1);
                mma16816(acc[0][0], acc[0][1], acc[0][2], acc[0][3],
                         al0, al1, al2, al3, bh0, bh1);
                mma16816(acc[0][0], acc[0][1], acc[0][2], acc[0][3],
                         ah0, ah1, ah2, ah3, bl0, bl1);
                mma16816(acc[1][0], acc[1][1], acc[1][2], acc[1][3],
                         ah0, ah1, ah2, ah3, bh2, bh3);
                mma16816(acc[1][0], acc[1][1], acc[1][2], acc[1][3],
                         al0, al1, al2, al3, bh2, bh3);
                mma16816(acc[1][0], acc[1][1], acc[1][2], acc[1][3],
                         ah0, ah1, ah2, ah3, bl2, bl3);
            }
        }
    }

    // ---- c,e reduce (8 lanes per B row, same warp)
    {
        float c = c_acc, e = e_acc;
#pragma unroll
        for (int o = 4; o; o >>= 1) {
            c += __shfl_xor_sync(0xffffffffu, c, o, 8);
            e += __shfl_xor_sync(0xffffffffu, e, o, 8);
        }
        if (bseg == 0) {
            *(float*)(smem + CE_C + brow * 4) = c;
            *(float*)(smem + CE_E + brow * 4) = e;
        }
    }
    // ---- mu/rs reduce (16 interleaved chains per warp)
    {
#pragma unroll
        for (int o = 16; o; o >>= 1) {
#pragma unroll
            for (int rr = 0; rr < 8; rr++) {
                s_acc[rr] += __shfl_xor_sync(0xffffffffu, s_acc[rr], o);
                q_acc[rr] += __shfl_xor_sync(0xffffffffu, q_acc[rr], o);
            }
        }
#pragma unroll
        for (int rr = 0; rr < 8; rr++) {
            if (lane == rr) {
                float mu = s_acc[rr] * (1.f / DD);
                float rs = rsqrtf(q_acc[rr] * (1.f / DD) - mu * mu + 1e-5f);
                *(float2*)(smem + MURS + (wid * 8 + rr) * 8) = make_float2(mu, rs);
            }
        }
    }
    __syncthreads();

    // ---- epilogue: out = rs*y + (e - mu*rs*c)
    {
        int r0l = rtile * 16 + (lane >> 2);
        float2 m0 = *(const float2*)(smem + MURS + r0l * 8);
        float2 m1 = *(const float2*)(smem + MURS + (r0l + 8) * 8);
        float mrc0 = -m0.x * m0.y, mrc1 = -m1.x * m1.y;
        size_t row0 = (size_t)bx * 64 + r0l;
        int c0 = (lane & 3) * 2;
        float* dst = chalf ? g_v : g_k;
#pragma unroll
        for (int t = 0; t < 2; t++) {
            int col = t * 8 + c0;
            int colg = chalf * 16 + col;
            float ca = *(const float*)(smem + CE_C + colg * 4);
            float cb = *(const float*)(smem + CE_C + (colg + 1) * 4);
            float ea = *(const float*)(smem + CE_E + colg * 4);
            float eb = *(const float*)(smem + CE_E + (colg + 1) * 4);
            *(float2*)(dst + row0 * SS + col) =
                make_float2(fmaf(m0.y, acc[t][0], fmaf(mrc0, ca, ea)),
                            fmaf(m0.y, acc[t][1], fmaf(mrc0, cb, eb)));
            *(float2*)(dst + (row0 + 8) * SS + col) =
                make_float2(fmaf(m1.y, acc[t][2], fmaf(mrc1, ca, ea)),
                            fmaf(m1.y, acc[t][3], fmaf(mrc1, cb, eb)));
        }
    }
}

// ---------------- Kernel B: attention streaming pass ------------------------
__global__ void __launch_bounds__(256) attn_kernel(float* __restrict__ out_attn,
                                                   int last) {
    __shared__ float sm_q[KK * SS];
    __shared__ ull sm_p2[KK * 257];          /* [k][n] padded: conflict-free */
    __shared__ float sm_v[NCHUNK * 18];
    __shared__ float2 sm_r[144];
    int tid = threadIdx.x;
    int b = blockIdx.y, nb = blockIdx.x;
    size_t nrow = (size_t)b * NN + (size_t)nb * NCHUNK + tid;

    // hoisted global loads
    ulonglong2 vr[4];
    {
        const ulonglong2* vs = (const ulonglong2*)(g_v + nrow * SS);
#pragma unroll
        for (int j = 0; j < 4; j++) vr[j] = vs[j];
    }
    union { float4 f4[4]; ull u[8]; } kf;
    {
        const float4* kf4 = (const float4*)(g_k + nrow * SS);
#pragma unroll
        for (int j = 0; j < 4; j++) kf.f4[j] = kf4[j];
    }
    if (tid < 32) ((float4*)sm_q)[tid] = ((const float4*)(g_q + b * 128))[tid];
    __syncthreads();

    {
        const float4* q4 = (const float4*)sm_q;
        float lg[KK];
#pragma unroll
        for (int kk = 0; kk < KK; kk++) {
            union { float4 f; ull u[2]; } qa, qb, qc, qd;
            qa.f = q4[kk * 4 + 0];
            qb.f = q4[kk * 4 + 1];
            qc.f = q4[kk * 4 + 2];
            qd.f = q4[kk * 4 + 3];
            ull a0 = ffma2(qa.u[0], kf.u[0], 0ull);
            ull a1 = ffma2(qa.u[1], kf.u[1], 0ull);
            a0 = ffma2(qb.u[0], kf.u[2], a0);
            a1 = ffma2(qb.u[1], kf.u[3], a1);
            a0 = ffma2(qc.u[0], kf.u[4], a0);
            a1 = ffma2(qc.u[1], kf.u[5], a1);
            a0 = ffma2(qd.u[0], kf.u[6], a0);
            a1 = ffma2(qd.u[1], kf.u[7], a1);
            lg[kk] = (ull_lo(a0) + ull_hi(a0)) + (ull_lo(a1) + ull_hi(a1));
        }
        float m = lg[0];
#pragma unroll
        for (int kk = 1; kk < KK; kk++) m = fmaxf(m, lg[kk]);
        float sum = 0.f;
#pragma unroll
        for (int kk = 0; kk < KK; kk++) {
            lg[kk] = __expf(lg[kk] - m);
            sum += lg[kk];
        }
        float inv = 1.f / sum;
#pragma unroll
        for (int kk = 0; kk < KK; kk++) {
            float p = lg[kk] * inv + 1e-8f;
            unsigned int pb = __float_as_uint(p);
            sm_p2[kk * 257 + tid] = ((ull)pb << 32) | pb;
            if (last) out_attn[((size_t)(b * KK + kk)) * NN + nb * NCHUNK + tid] = p;
        }
    }
    // spill v registers to smem (row n = tid)
    {
        ull* vd = (ull*)&sm_v[tid * 18];
#pragma unroll
        for (int j = 0; j < 4; j++) {
            vd[2 * j] = vr[j].x;
            vd[2 * j + 1] = vr[j].y;
        }
        sm_v[tid * 18 + 16] = 1.f;
        sm_v[tid * 18 + 17] = 0.f;
    }
    __syncthreads();

    // numer + denom reduce: 144 threads, f32x2, 2 halves of 128 n each
    if (tid < 144) {
        int half = (tid >= 72);
        int r = tid - half * 72;
        int k = r / 9, c = r % 9;
        const ull* prow = sm_p2 + k * 257;
        ull a0 = 0ull, a1 = 0ull, a2 = 0ull, a3 = 0ull;
        int n0 = half * 128;
#pragma unroll 2
        for (int n = n0; n < n0 + 128; n += 4) {
            a0 = ffma2(prow[n], *(const ull*)&sm_v[n * 18 + 2 * c], a0);
            a1 = ffma2(prow[n + 1], *(const ull*)&sm_v[(n + 1) * 18 + 2 * c], a1);
            a2 = ffma2(prow[n + 2], *(const ull*)&sm_v[(n + 2) * 18 + 2 * c], a2);
            a3 = ffma2(prow[n + 3], *(const ull*)&sm_v[(n + 3) * 18 + 2 * c], a3);
        }
        sm_r[tid] = make_float2((ull_lo(a0) + ull_lo(a1)) + (ull_lo(a2) + ull_lo(a3)),
                                (ull_hi(a0) + ull_hi(a1)) + (ull_hi(a2) + ull_hi(a3)));
    }
    __syncthreads();
    if (tid < 72) {
        float2 A = sm_r[tid], B = sm_r[72 + tid];
        float lo = A.x + B.x, hi = A.y + B.y;
        int k = tid / 9, c = tid % 9;
        float* gp = g_partial + ((size_t)b * NBLK + nb) * PART;
        if (c < 8) {
            gp[k * SS + 2 * c] = lo;
            gp[k * SS + 2 * c + 1] = hi;
        } else {
            gp[128 + k] = lo;
        }
    }
}

// ---------------- Kernel C: per-(b,k) reduce + GRU + LN + MLP + next-q ------
__global__ void __launch_bounds__(128) update_kernel(
    const float* __restrict__ init_slots, const float* __restrict__ w_ih,
    const float* __restrict__ w_hh, const float* __restrict__ b_ih,
    const float* __restrict__ b_hh, const float* __restrict__ ln_m_w,
    const float* __restrict__ ln_m_b, const float* __restrict__ mlp_w1,
    const float* __restrict__ mlp_b1, const float* __restrict__ mlp_w2,
    const float* __restrict__ mlp_b2, const float* __restrict__ ln_s_w,
    const float* __restrict__ ln_s_b, const float* __restrict__ wq,
    float* __restrict__ out_slots, int iter, int last) {
    __shared__ float s_num[16], s_upd[16], s_hp[16], s_h[16], s_y[16];
    __shared__ float s_h1[128], s_ns[16];
    __shared__ float s_den;
    int t = threadIdx.x;
    int b = blockIdx.x >> 3, k = blockIdx.x & 7;
    const float* slots_in =
        (iter == 0) ? (init_slots + b * 128) : (g_slots + b * 128);

    if (t < 17) {
        float s = 0.f;
        int off = (t < 16) ? (k * SS + t) : (128 + k);
#pragma unroll
        for (int j = 0; j < NBLK; j++)
            s += g_partial[((size_t)(b * NBLK + j)) * PART + off];
        if (t < 16) s_num[t] = s;
        else { s_den = s; g_denom[b * KK + k] = s; }
    }
    if (t < 16) s_hp[t] = slots_in[k * SS + t];
    __syncthreads();
    if (t < 16) s_upd[t] = s_num[t] / s_den;
    __syncthreads();

    // GRU (torch gate order [r,z,n])
    if (t < 16) {
        float ir = b_ih[t], iz = b_ih[SS + t], inn = b_ih[2 * SS + t];
        float hr = b_hh[t], hz = b_hh[SS + t], hn = b_hh[2 * SS + t];
#pragma unroll
        for (int tt = 0; tt < SS; tt++) {
            float u = s_upd[tt], hp = s_hp[tt];
            ir += w_ih[t * SS + tt] * u;
            iz += w_ih[(SS + t) * SS + tt] * u;
            inn += w_ih[(2 * SS + t) * SS + tt] * u;
            hr += w_hh[t * SS + tt] * hp;
            hz += w_hh[(SS + t) * SS + tt] * hp;
            hn += w_hh[(2 * SS + t) * SS + tt] * hp;
        }
        float r = 1.f / (1.f + __expf(-(ir + hr)));
        float z = 1.f / (1.f + __expf(-(iz + hz)));
        float n = tanhf(inn + r * hn);
        float h = (1.f - z) * n + z * s_hp[t];
        s_h[t] = h;
        float sum = h, sq = h * h;
#pragma unroll
        for (int o = 8; o; o >>= 1) {
            sum += __shfl_xor_sync(0xffffu, sum, o, 16);
            sq += __shfl_xor_sync(0xffffu, sq, o, 16);
        }
        float mu = sum * (1.f / SS);
        float rs = rsqrtf(sq * (1.f / SS) - mu * mu + 1e-5f);
        s_y[t] = (h - mu) * rs * ln_m_w[t] + ln_m_b[t];
    }
    __syncthreads();

    // MLP1: one hidden unit per thread
    {
        float a = mlp_b1[t];
#pragma unroll
        for (int s = 0; s < SS; s++) a += mlp_w1[t * SS + s] * s_y[s];
        s_h1[t] = fmaxf(a, 0.f);
    }
    __syncthreads();

    // MLP2: 16 outputs x 8 threads, width-8 shfl reduce
    {
        int s = t >> 3, part = t & 7;
        float a = 0.f;
#pragma unroll
        for (int j = 0; j < 16; j++)
            a += mlp_w2[s * HH + part * 16 + j] * s_h1[part * 16 + j];
        a += __shfl_xor_sync(0xffffffffu, a, 4, 8);
        a += __shfl_xor_sync(0xffffffffu, a, 2, 8);
        a += __shfl_xor_sync(0xffffffffu, a, 1, 8);
        if (part == 0) {
            float ns = s_h[s] + mlp_b2[s] + a;
            s_ns[s] = ns;
            g_slots[b * 128 + k * SS + s] = ns;
            if (last) out_slots[b * 128 + k * SS + s] = ns;
        }
    }
    __syncthreads();

    if (!last && t < 16) {
        float v = s_ns[t];
        float sum = v, sq = v * v;
#pragma unroll
        for (int o = 8; o; o >>= 1) {
            sum += __shfl_xor_sync(0xffffu, sum, o, 16);
            sq += __shfl_xor_sync(0xffffu, sq, o, 16);
        }
        float mu = sum * (1.f / SS);
        float rs = rsqrtf(sq * (1.f / SS) - mu * mu + 1e-5f);
        s_y[t] = (v - mu) * rs * ln_s_w[t] + ln_s_b[t];
        __syncwarp(0xffffu);
        float a = 0.f;
#pragma unroll
        for (int s = 0; s < SS; s++) a += s_y[s] * wq[t * SS + s];
        g_q[b * 128 + k * SS + t] = a * 0.25f;
    }
}

// ---------------- Kernel D: normalize emitted attention (float4) ------------
__global__ void __launch_bounds__(256) norm_attn_kernel(float4* __restrict__ out_attn) {
    int i = blockIdx.x * 256 + threadIdx.x;
    float4 p = out_attn[i];
    float inv = 1.f / g_denom[i >> 10];
    p.x *= inv; p.y *= inv; p.z *= inv; p.w *= inv;
    out_attn[i] = p;
}

// ---------------- launch ----------------
extern "C" void kernel_launch(void* const* d_in, const int* in_sizes, int n_in,
                              void* d_out, int out_size) {
    (void)in_sizes; (void)n_in; (void)out_size;
    const float* inputs     = (const float*)d_in[0];
    const float* init_slots = (const float*)d_in[1];
    const float* ln_in_w    = (const float*)d_in[2];
    const float* ln_in_b    = (const float*)d_in[3];
    const float* ln_s_w     = (const float*)d_in[4];
    const float* ln_s_b     = (const float*)d_in[5];
    const float* ln_m_w     = (const float*)d_in[6];
    const float* ln_m_b     = (const float*)d_in[7];
    const float* wq         = (const float*)d_in[8];
    const float* wk         = (const float*)d_in[9];
    const float* wv         = (const float*)d_in[10];
    const float* w_ih       = (const float*)d_in[11];
    const float* w_hh       = (const float*)d_in[12];
    const float* b_ih       = (const float*)d_in[13];
    const float* b_hh       = (const float*)d_in[14];
    const float* mlp_w1     = (const float*)d_in[15];
    const float* mlp_b1     = (const float*)d_in[16];
    const float* mlp_w2     = (const float*)d_in[17];
    const float* mlp_b2     = (const float*)d_in[18];
    float* out = (float*)d_out;
    float* out_slots = out;
    float* out_attn = out + BB * KK * SS;

    cudaFuncSetAttribute(ln_proj_tc, cudaFuncAttributeMaxDynamicSharedMemorySize,
                         SMEM_LN);
    ln_proj_tc<<<NTOT, 256, SMEM_LN>>>(inputs, ln_in_w, ln_in_b, wk, wv,
                                       init_slots, ln_s_w, ln_s_b, wq);
    for (int it = 0; it < 3; it++) {
        int last = (it == 2) ? 1 : 0;
        dim3 gb(NBLK, BB);
        attn_kernel<<<gb, 256>>>(out_attn, last);
        update_kernel<<<BB * KK, 128>>>(init_slots, w_ih, w_hh, b_ih, b_hh,
                                        ln_m_w, ln_m_b, mlp_w1, mlp_b1, mlp_w2,
                                        mlp_b2, ln_s_w, ln_s_b, wq, out_slots,
                                        it, last);
    }
    norm_attn_kernel<<<(BB * KK * NN) / 1024, 256>>>((float4*)out_attn);
}

// round 15
// speedup vs baseline: 1.0049x; 1.0049x over previous
#include <cuda_runtime.h>
#include <cuda_bf16.h>
#include <cstdint>
#include <math.h>

#define BB 32
#define NN 4096
#define DD 256
#define SS 16
#define KK 8
#define HH 128
#define NCHUNK 256
#define NBLK (NN / NCHUNK)      /* 16 chunks per batch */
#define PART (KK * SS + KK)     /* 136 partials per chunk */
#define NPROJ ((BB * NN) / 64)  /* 2048 projection blocks */
#define NTOT (NPROJ + BB)

// ---------------- device scratch ----------------
__device__ __align__(16) float g_k[BB * NN * SS];
__device__ __align__(16) float g_v[BB * NN * SS];
__device__ __align__(16) float g_slots[BB * KK * SS];
__device__ __align__(16) float g_q[BB * KK * SS];
__device__ __align__(16) float g_partial[BB * NBLK * PART];
__device__ __align__(16) float g_denom[BB * KK];

// ---------------- helpers ----------------
typedef unsigned long long ull;
__device__ __forceinline__ ull ffma2(ull a, ull b, ull c) {
    ull d;
    asm("fma.rn.f32x2 %0, %1, %2, %3;" : "=l"(d) : "l"(a), "l"(b), "l"(c));
    return d;
}
__device__ __forceinline__ float ull_lo(ull u) {
    return __uint_as_float((unsigned int)(u & 0xffffffffull));
}
__device__ __forceinline__ float ull_hi(ull u) {
    return __uint_as_float((unsigned int)(u >> 32));
}

__device__ __forceinline__ void mma16816(float& c0, float& c1, float& c2,
                                         float& c3, uint32_t a0, uint32_t a1,
                                         uint32_t a2, uint32_t a3, uint32_t b0,
                                         uint32_t b1) {
    asm volatile(
        "mma.sync.aligned.m16n8k16.row.col.f32.bf16.bf16.f32 "
        "{%0,%1,%2,%3}, {%4,%5,%6,%7}, {%8,%9}, {%0,%1,%2,%3};"
        : "+f"(c0), "+f"(c1), "+f"(c2), "+f"(c3)
        : "r"(a0), "r"(a1), "r"(a2), "r"(a3), "r"(b0), "r"(b1));
}
__device__ __forceinline__ void ldm4(uint32_t& r0, uint32_t& r1, uint32_t& r2,
                                     uint32_t& r3, uint32_t addr) {
    asm volatile(
        "ldmatrix.sync.aligned.m8n8.x4.shared.b16 {%0,%1,%2,%3}, [%4];"
        : "=r"(r0), "=r"(r1), "=r"(r2), "=r"(r3) : "r"(addr));
}
__device__ __forceinline__ ull pack_hi_lo(float a, float b, float c, float d,
                                          ull& lo_out) {
    __nv_bfloat162 h0 = __floats2bfloat162_rn(a, b);
    __nv_bfloat162 h1 = __floats2bfloat162_rn(c, d);
    __nv_bfloat162 l0 = __floats2bfloat162_rn(a - __low2float(h0), b - __high2float(h0));
    __nv_bfloat162 l1 = __floats2bfloat162_rn(c - __low2float(h1), d - __high2float(h1));
    lo_out = ((ull)(*(uint32_t*)&l1) << 32) | (*(uint32_t*)&l0);
    return ((ull)(*(uint32_t*)&h1) << 32) | (*(uint32_t*)&h0);
}
__device__ __forceinline__ uint32_t pack2(float a, float b, uint32_t& lo) {
    __nv_bfloat162 h = __floats2bfloat162_rn(a, b);
    __nv_bfloat162 l = __floats2bfloat162_rn(a - __low2float(h), b - __high2float(h));
    lo = *(uint32_t*)&l;
    return *(uint32_t*)&h;
}

// ---------------- Kernel A: single-pass pipelined bf16 HMMA, epilogue LN ----
// k = rs*(x@W') + (e - mu*rs*c),  W' = lnw (.) Wk,  c = sum_d W', e = sum_d lnb*Wk
// 64 rows/CTA, 256 threads, K in 4 quarters of 64. Quarter h+1's x loads are
// issued before quarter h's MMA so DRAM latency hides behind barrier + MMA.
#define RSTR 144
#define A_HI 0
#define A_LO (64 * RSTR)                 /* 9216 */
#define B_HI (2 * 64 * RSTR)             /* 18432 */
#define B_LO (B_HI + 32 * RSTR)          /* 23040 */
#define MURS (B_LO + 32 * RSTR)          /* 27648: 64 x float2 */
#define CE_C (MURS + 512)                /* 28160: 32 floats */
#define CE_E (CE_C + 128)                /* 28288: 32 floats */
#define SMEM_LN (CE_E + 128)             /* 28416 */

__global__ void __launch_bounds__(256, 4) ln_proj_tc(
    const float* __restrict__ x, const float* __restrict__ lnw,
    const float* __restrict__ lnb, const float* __restrict__ wk,
    const float* __restrict__ wvm, const float* __restrict__ init_slots,
    const float* __restrict__ ln_s_w, const float* __restrict__ ln_s_b,
    const float* __restrict__ wq) {
    extern __shared__ char smem[];
    int tid = threadIdx.x, wid = tid >> 5, lane = tid & 31;
    int bx = blockIdx.x;

    // ---- fused q_init blocks ----
    if (bx >= NPROJ) {
        float* smq = (float*)smem;
        int b = bx - NPROJ;
        if (tid < 128) {
            int s = tid & 15;
            float v = init_slots[b * 128 + tid];
            float sum = v, sq = v * v;
#pragma unroll
            for (int o = 8; o; o >>= 1) {
                sum += __shfl_xor_sync(0xffffffffu, sum, o, 16);
                sq += __shfl_xor_sync(0xffffffffu, sq, o, 16);
            }
            float mu = sum * (1.f / SS);
            float rs = rsqrtf(sq * (1.f / SS) - mu * mu + 1e-5f);
            smq[tid] = (v - mu) * rs * ln_s_w[s] + ln_s_b[s];
        }
        __syncthreads();
        if (tid < 128) {
            int k = tid >> 4, t = tid & 15;
            float a = 0.f;
#pragma unroll
            for (int ss = 0; ss < SS; ss++) a += smq[k * SS + ss] * wq[t * SS + ss];
            g_q[b * 128 + tid] = a * 0.25f;
        }
        return;
    }

    uint32_t sb = (uint32_t)__cvta_generic_to_shared(smem);
    int rtile = wid >> 1, chalf = wid & 1;
    int brow = tid >> 3, bseg = tid & 7;
    const float* wsrc_base =
        ((brow < SS) ? (wk + brow * DD) : (wvm + (brow - SS) * DD)) + bseg * 8;
    const float2* xbase =
        (const float2*)(x + ((size_t)bx * 64 + wid * 8) * DD) + lane;

    float s_acc[8], q_acc[8];
#pragma unroll
    for (int rr = 0; rr < 8; rr++) { s_acc[rr] = 0.f; q_acc[rr] = 0.f; }
    float c_acc = 0.f, e_acc = 0.f;
    float acc[2][4];
#pragma unroll
    for (int t = 0; t < 2; t++)
#pragma unroll
        for (int j = 0; j < 4; j++) acc[t][j] = 0.f;

    // ---- prologue: quarter-0 x loads (only exposed DRAM latency)
    float2 xa[8];
#pragma unroll
    for (int rr = 0; rr < 8; rr++) xa[rr] = xbase[rr * 128];

#pragma unroll 1
    for (int h = 0; h < 4; h++) {
        __syncthreads();  // previous quarter's MMA reads done

        // ---- stage B: W' = lnw .* W row-slice, bf16 split; accumulate c,e
        {
            const float* src = wsrc_base + h * 64;
            char* bh = smem + B_HI + brow * RSTR + bseg * 16;
            char* bl = smem + B_LO + brow * RSTR + bseg * 16;
#pragma unroll
            for (int i = 0; i < 2; i++) {
                float4 f = *(const float4*)(src + i * 4);
                float4 w = *(const float4*)(lnw + h * 64 + bseg * 8 + i * 4);
                float4 b = *(const float4*)(lnb + h * 64 + bseg * 8 + i * 4);
                float px = f.x * w.x, py = f.y * w.y, pz = f.z * w.z, pw = f.w * w.w;
                c_acc += (px + py) + (pz + pw);
                e_acc += (f.x * b.x + f.y * b.y) + (f.z * b.z + f.w * b.w);
                ull lo;
                ull hi = pack_hi_lo(px, py, pz, pw, lo);
                *(ull*)(bh + i * 8) = hi;
                *(ull*)(bl + i * 8) = lo;
            }
        }

        // ---- stage A from prefetched regs; then issue next quarter's loads
        {
#pragma unroll
            for (int rr = 0; rr < 8; rr++) {
                float2 a = xa[rr];
                s_acc[rr] += a.x + a.y;
                q_acc[rr] += a.x * a.x + a.y * a.y;
                uint32_t lo;
                uint32_t hi = pack2(a.x, a.y, lo);
                char* ah = smem + A_HI + (wid * 8 + rr) * RSTR + 4 * lane;
                *(uint32_t*)ah = hi;
                *(uint32_t*)(ah + (A_LO - A_HI)) = lo;
            }
            if (h < 3) {
#pragma unroll
                for (int rr = 0; rr < 8; rr++)
                    xa[rr] = xbase[rr * 128 + (h + 1) * 32];
            }
        }
        __syncthreads();

        // ---- MMA: 4 k-steps, ldmatrix fragments
        {
            int tr = lane & 7, sel = lane >> 3;
            uint32_t a_addr = sb + A_HI +
                              (uint32_t)(rtile * 16 + tr + ((sel & 1) << 3)) * RSTR +
                              ((sel >> 1) << 4);
            uint32_t b_addr = sb + B_HI +
                              (uint32_t)(chalf * 16 + tr + ((sel >> 1) << 3)) * RSTR +
                              ((sel & 1) << 4);
#pragma unroll
            for (int ks = 0; ks < 4; ks++) {
                uint32_t ah0, ah1, ah2, ah3, al0, al1, al2, al3;
                uint32_t bh0, bh1, bh2, bh3, bl0, bl1, bl2, bl3;
                ldm4(ah0, ah1, ah2, ah3, a_addr + ks * 32);
                ldm4(al0, al1, al2, al3, a_addr + (A_LO - A_HI) + ks * 32);
                ldm4(bh0, bh1, bh2, bh3, b_addr + ks * 32);
                ldm4(bl0, bl1, bl2, bl3, b_addr + (B_LO - B_HI) + ks * 32);
                mma16816(acc[0][0], acc[0][1], acc[0][2], acc[0][3],
                         ah0, ah1, ah2, ah3, bh0, bh1);
                mma16816(acc[0][0], acc[0][1], acc[0][2], acc[0][3],
                         al0, al1, al2, al3, bh0, bh1);
                mma16816(acc[0][0], acc[0][1], acc[0][2], acc[0][3],
                         ah0, ah1, ah2, ah3, bl0, bl1);
                mma16816(acc[1][0], acc[1][1], acc[1][2], acc[1][3],
                         ah0, ah1, ah2, ah3, bh2, bh3);
                mma16816(acc[1][0], acc[1][1], acc[1][2], acc[1][3],
                         al0, al1, al2, al3, bh2, bh3);
                mma16816(acc[1][0], acc[1][1], acc[1][2], acc[1][3],
                         ah0, ah1, ah2, ah3, bl2, bl3);
            }
        }
    }

    // ---- c,e reduce (8 lanes per B row, same warp)
    {
        float c = c_acc, e = e_acc;
#pragma unroll
        for (int o = 4; o; o >>= 1) {
            c += __shfl_xor_sync(0xffffffffu, c, o, 8);
            e += __shfl_xor_sync(0xffffffffu, e, o, 8);
        }
        if (bseg == 0) {
            *(float*)(smem + CE_C + brow * 4) = c;
            *(float*)(smem + CE_E + brow * 4) = e;
        }
    }
    // ---- mu/rs reduce (16 interleaved chains per warp)
    {
#pragma unroll
        for (int o = 16; o; o >>= 1) {
#pragma unroll
            for (int rr = 0; rr < 8; rr++) {
                s_acc[rr] += __shfl_xor_sync(0xffffffffu, s_acc[rr], o);
                q_acc[rr] += __shfl_xor_sync(0xffffffffu, q_acc[rr], o);
            }
        }
#pragma unroll
        for (int rr = 0; rr < 8; rr++) {
            if (lane == rr) {
                float mu = s_acc[rr] * (1.f / DD);
                float rs = rsqrtf(q_acc[rr] * (1.f / DD) - mu * mu + 1e-5f);
                *(float2*)(smem + MURS + (wid * 8 + rr) * 8) = make_float2(mu, rs);
            }
        }
    }
    __syncthreads();

    // ---- epilogue: out = rs*y + (e - mu*rs*c)
    {
        int r0l = rtile * 16 + (lane >> 2);
        float2 m0 = *(const float2*)(smem + MURS + r0l * 8);
        float2 m1 = *(const float2*)(smem + MURS + (r0l + 8) * 8);
        float mrc0 = -m0.x * m0.y, mrc1 = -m1.x * m1.y;
        size_t row0 = (size_t)bx * 64 + r0l;
        int c0 = (lane & 3) * 2;
        float* dst = chalf ? g_v : g_k;
#pragma unroll
        for (int t = 0; t < 2; t++) {
            int col = t * 8 + c0;
            int colg = chalf * 16 + col;
            float ca = *(const float*)(smem + CE_C + colg * 4);
            float cb = *(const float*)(smem + CE_C + (colg + 1) * 4);
            float ea = *(const float*)(smem + CE_E + colg * 4);
            float eb = *(const float*)(smem + CE_E + (colg + 1) * 4);
            *(float2*)(dst + row0 * SS + col) =
                make_float2(fmaf(m0.y, acc[t][0], fmaf(mrc0, ca, ea)),
                            fmaf(m0.y, acc[t][1], fmaf(mrc0, cb, eb)));
            *(float2*)(dst + (row0 + 8) * SS + col) =
                make_float2(fmaf(m1.y, acc[t][2], fmaf(mrc1, ca, ea)),
                            fmaf(m1.y, acc[t][3], fmaf(mrc1, cb, eb)));
        }
    }
}

// ---------------- Kernel B: attention streaming pass ------------------------
__global__ void __launch_bounds__(256) attn_kernel(float* __restrict__ out_attn,
                                                   int last) {
    __shared__ float sm_q[KK * SS];
    __shared__ ull sm_p2[KK * 257];          /* [k][n] padded: conflict-free */
    __shared__ float sm_v[NCHUNK * 18];
    __shared__ float2 sm_r[144];
    int tid = threadIdx.x;
    int b = blockIdx.y, nb = blockIdx.x;
    size_t nrow = (size_t)b * NN + (size_t)nb * NCHUNK + tid;

    // hoisted global loads
    ulonglong2 vr[4];
    {
        const ulonglong2* vs = (const ulonglong2*)(g_v + nrow * SS);
#pragma unroll
        for (int j = 0; j < 4; j++) vr[j] = vs[j];
    }
    union { float4 f4[4]; ull u[8]; } kf;
    {
        const float4* kf4 = (const float4*)(g_k + nrow * SS);
#pragma unroll
        for (int j = 0; j < 4; j++) kf.f4[j] = kf4[j];
    }
    if (tid < 32) ((float4*)sm_q)[tid] = ((const float4*)(g_q + b * 128))[tid];
    __syncthreads();

    {
        const float4* q4 = (const float4*)sm_q;
        float lg[KK];
#pragma unroll
        for (int kk = 0; kk < KK; kk++) {
            union { float4 f; ull u[2]; } qa, qb, qc, qd;
            qa.f = q4[kk * 4 + 0];
            qb.f = q4[kk * 4 + 1];
            qc.f = q4[kk * 4 + 2];
            qd.f = q4[kk * 4 + 3];
            ull a0 = ffma2(qa.u[0], kf.u[0], 0ull);
            ull a1 = ffma2(qa.u[1], kf.u[1], 0ull);
            a0 = ffma2(qb.u[0], kf.u[2], a0);
            a1 = ffma2(qb.u[1], kf.u[3], a1);
            a0 = ffma2(qc.u[0], kf.u[4], a0);
            a1 = ffma2(qc.u[1], kf.u[5], a1);
            a0 = ffma2(qd.u[0], kf.u[6], a0);
            a1 = ffma2(qd.u[1], kf.u[7], a1);
            lg[kk] = (ull_lo(a0) + ull_hi(a0)) + (ull_lo(a1) + ull_hi(a1));
        }
        float m = lg[0];
#pragma unroll
        for (int kk = 1; kk < KK; kk++) m = fmaxf(m, lg[kk]);
        float sum = 0.f;
#pragma unroll
        for (int kk = 0; kk < KK; kk++) {
            lg[kk] = __expf(lg[kk] - m);
            sum += lg[kk];
        }
        float inv = 1.f / sum;
#pragma unroll
        for (int kk = 0; kk < KK; kk++) {
            float p = lg[kk] * inv + 1e-8f;
            unsigned int pb = __float_as_uint(p);
            sm_p2[kk * 257 + tid] = ((ull)pb << 32) | pb;
            if (last) out_attn[((size_t)(b * KK + kk)) * NN + nb * NCHUNK + tid] = p;
        }
    }
    // spill v registers to smem (row n = tid)
    {
        ull* vd = (ull*)&sm_v[tid * 18];
#pragma unroll
        for (int j = 0; j < 4; j++) {
            vd[2 * j] = vr[j].x;
            vd[2 * j + 1] = vr[j].y;
        }
        sm_v[tid * 18 + 16] = 1.f;
        sm_v[tid * 18 + 17] = 0.f;
    }
    __syncthreads();

    // numer + denom reduce: 144 threads, f32x2, 2 halves of 128 n each
    if (tid < 144) {
        int half = (tid >= 72);
        int r = tid - half * 72;
        int k = r / 9, c = r % 9;
        const ull* prow = sm_p2 + k * 257;
        ull a0 = 0ull, a1 = 0ull, a2 = 0ull, a3 = 0ull;
        int n0 = half * 128;
#pragma unroll 2
        for (int n = n0; n < n0 + 128; n += 4) {
            a0 = ffma2(prow[n], *(const ull*)&sm_v[n * 18 + 2 * c], a0);
            a1 = ffma2(prow[n + 1], *(const ull*)&sm_v[(n + 1) * 18 + 2 * c], a1);
            a2 = ffma2(prow[n + 2], *(const ull*)&sm_v[(n + 2) * 18 + 2 * c], a2);
            a3 = ffma2(prow[n + 3], *(const ull*)&sm_v[(n + 3) * 18 + 2 * c], a3);
        }
        sm_r[tid] = make_float2((ull_lo(a0) + ull_lo(a1)) + (ull_lo(a2) + ull_lo(a3)),
                                (ull_hi(a0) + ull_hi(a1)) + (ull_hi(a2) + ull_hi(a3)));
    }
    __syncthreads();
    if (tid < 72) {
        float2 A = sm_r[tid], B = sm_r[72 + tid];
        float lo = A.x + B.x, hi = A.y + B.y;
        int k = tid / 9, c = tid % 9;
        float* gp = g_partial + ((size_t)b * NBLK + nb) * PART;
        if (c < 8) {
            gp[k * SS + 2 * c] = lo;
            gp[k * SS + 2 * c + 1] = hi;
        } else {
            gp[128 + k] = lo;
        }
    }
}

// ---------------- Kernel C: per-(b,k) reduce + GRU + LN + MLP + next-q ------
__global__ void __launch_bounds__(128) update_kernel(
    const float* __restrict__ init_slots, const float* __restrict__ w_ih,
    const float* __restrict__ w_hh, const float* __restrict__ b_ih,
    const float* __restrict__ b_hh, const float* __restrict__ ln_m_w,
    const float* __restrict__ ln_m_b, const float* __restrict__ mlp_w1,
    const float* __restrict__ mlp_b1, const float* __restrict__ mlp_w2,
    const float* __restrict__ mlp_b2, const float* __restrict__ ln_s_w,
    const float* __restrict__ ln_s_b, const float* __restrict__ wq,
    float* __restrict__ out_slots, int iter, int last) {
    __shared__ float s_num[16], s_upd[16], s_hp[16], s_h[16], s_y[16];
    __shared__ float s_h1[128], s_ns[16];
    __shared__ float s_den;
    int t = threadIdx.x;
    int b = blockIdx.x >> 3, k = blockIdx.x & 7;
    const float* slots_in =
        (iter == 0) ? (init_slots + b * 128) : (g_slots + b * 128);

    if (t < 17) {
        float s = 0.f;
        int off = (t < 16) ? (k * SS + t) : (128 + k);
#pragma unroll
        for (int j = 0; j < NBLK; j++)
            s += g_partial[((size_t)(b * NBLK + j)) * PART + off];
        if (t < 16) s_num[t] = s;
        else { s_den = s; g_denom[b * KK + k] = s; }
    }
    if (t < 16) s_hp[t] = slots_in[k * SS + t];
    __syncthreads();
    if (t < 16) s_upd[t] = s_num[t] / s_den;
    __syncthreads();

    // GRU (torch gate order [r,z,n])
    if (t < 16) {
        float ir = b_ih[t], iz = b_ih[SS + t], inn = b_ih[2 * SS + t];
        float hr = b_hh[t], hz = b_hh[SS + t], hn = b_hh[2 * SS + t];
#pragma unroll
        for (int tt = 0; tt < SS; tt++) {
            float u = s_upd[tt], hp = s_hp[tt];
            ir += w_ih[t * SS + tt] * u;
            iz += w_ih[(SS + t) * SS + tt] * u;
            inn += w_ih[(2 * SS + t) * SS + tt] * u;
            hr += w_hh[t * SS + tt] * hp;
            hz += w_hh[(SS + t) * SS + tt] * hp;
            hn += w_hh[(2 * SS + t) * SS + tt] * hp;
        }
        float r = 1.f / (1.f + __expf(-(ir + hr)));
        float z = 1.f / (1.f + __expf(-(iz + hz)));
        float n = tanhf(inn + r * hn);
        float h = (1.f - z) * n + z * s_hp[t];
        s_h[t] = h;
        float sum = h, sq = h * h;
#pragma unroll
        for (int o = 8; o; o >>= 1) {
            sum += __shfl_xor_sync(0xffffu, sum, o, 16);
            sq += __shfl_xor_sync(0xffffu, sq, o, 16);
        }
        float mu = sum * (1.f / SS);
        float rs = rsqrtf(sq * (1.f / SS) - mu * mu + 1e-5f);
        s_y[t] = (h - mu) * rs * ln_m_w[t] + ln_m_b[t];
    }
    __syncthreads();

    // MLP1: one hidden unit per thread
    {
        float a = mlp_b1[t];
#pragma unroll
        for (int s = 0; s < SS; s++) a += mlp_w1[t * SS + s] * s_y[s];
        s_h1[t] = fmaxf(a, 0.f);
    }
    __syncthreads();

    // MLP2: 16 outputs x 8 threads, width-8 shfl reduce
    {
        int s = t >> 3, part = t & 7;
        float a = 0.f;
#pragma unroll
        for (int j = 0; j < 16; j++)
            a += mlp_w2[s * HH + part * 16 + j] * s_h1[part * 16 + j];
        a += __shfl_xor_sync(0xffffffffu, a, 4, 8);
        a += __shfl_xor_sync(0xffffffffu, a, 2, 8);
        a += __shfl_xor_sync(0xffffffffu, a, 1, 8);
        if (part == 0) {
            float ns = s_h[s] + mlp_b2[s] + a;
            s_ns[s] = ns;
            g_slots[b * 128 + k * SS + s] = ns;
            if (last) out_slots[b * 128 + k * SS + s] = ns;
        }
    }
    __syncthreads();

    if (!last && t < 16) {
        float v = s_ns[t];
        float sum = v, sq = v * v;
#pragma unroll
        for (int o = 8; o; o >>= 1) {
            sum += __shfl_xor_sync(0xffffu, sum, o, 16);
            sq += __shfl_xor_sync(0xffffu, sq, o, 16);
        }
        float mu = sum * (1.f / SS);
        float rs = rsqrtf(sq * (1.f / SS) - mu * mu + 1e-5f);
        s_y[t] = (v - mu) * rs * ln_s_w[t] + ln_s_b[t];
        __syncwarp(0xffffu);
        float a = 0.f;
#pragma unroll
        for (int s = 0; s < SS; s++) a += s_y[s] * wq[t * SS + s];
        g_q[b * 128 + k * SS + t] = a * 0.25f;
    }
}

// ---------------- Kernel D: normalize emitted attention (float4) ------------
__global__ void __launch_bounds__(256) norm_attn_kernel(float4* __restrict__ out_attn) {
    int i = blockIdx.x * 256 + threadIdx.x;
    float4 p = out_attn[i];
    float inv = 1.f / g_denom[i >> 10];
    p.x *= inv; p.y *= inv; p.z *= inv; p.w *= inv;
    out_attn[i] = p;
}

// ---------------- launch ----------------
extern "C" void kernel_launch(void* const* d_in, const int* in_sizes, int n_in,
                              void* d_out, int out_size) {
    (void)in_sizes; (void)n_in; (void)out_size;
    const float* inputs     = (const float*)d_in[0];
    const float* init_slots = (const float*)d_in[1];
    const float* ln_in_w    = (const float*)d_in[2];
    const float* ln_in_b    = (const float*)d_in[3];
    const float* ln_s_w     = (const float*)d_in[4];
    const float* ln_s_b     = (const float*)d_in[5];
    const float* ln_m_w     = (const float*)d_in[6];
    const float* ln_m_b     = (const float*)d_in[7];
    const float* wq         = (const float*)d_in[8];
    const float* wk         = (const float*)d_in[9];
    const float* wv         = (const float*)d_in[10];
    const float* w_ih       = (const float*)d_in[11];
    const float* w_hh       = (const float*)d_in[12];
    const float* b_ih       = (const float*)d_in[13];
    const float* b_hh       = (const float*)d_in[14];
    const float* mlp_w1     = (const float*)d_in[15];
    const float* mlp_b1     = (const float*)d_in[16];
    const float* mlp_w2     = (const float*)d_in[17];
    const float* mlp_b2     = (const float*)d_in[18];
    float* out = (float*)d_out;
    float* out_slots = out;
    float* out_attn = out + BB * KK * SS;

    cudaFuncSetAttribute(ln_proj_tc, cudaFuncAttributeMaxDynamicSharedMemorySize,
                         SMEM_LN);
    ln_proj_tc<<<NTOT, 256, SMEM_LN>>>(inputs, ln_in_w, ln_in_b, wk, wv,
                                       init_slots, ln_s_w, ln_s_b, wq);
    for (int it = 0; it < 3; it++) {
        int last = (it == 2) ? 1 : 0;
        dim3 gb(NBLK, BB);
        attn_kernel<<<gb, 256>>>(out_attn, last);
        update_kernel<<<BB * KK, 128>>>(init_slots, w_ih, w_hh, b_ih, b_hh,
                                        ln_m_w, ln_m_b, mlp_w1, mlp_b1, mlp_w2,
                                        mlp_b2, ln_s_w, ln_s_b, wq, out_slots,
                                        it, last);
    }
    norm_attn_kernel<<<(BB * KK * NN) / 1024, 256>>>((float4*)out_attn);
}

// round 16
// speedup vs baseline: 1.1793x; 1.1736x over previous
#include <cuda_runtime.h>
#include <cuda_bf16.h>
#include <cstdint>
#include <math.h>

#define BB 32
#define NN 4096
#define DD 256
#define SS 16
#define KK 8
#define HH 128
#define NCHUNK 256
#define NBLK (NN / NCHUNK)      /* 16 chunks per batch */
#define PART (KK * SS + KK)     /* 136 partials per chunk */
#define NPROJ ((BB * NN) / 64)  /* 2048 projection blocks */
#define NTOT (NPROJ + BB)

// ---------------- device scratch ----------------
__device__ __align__(16) float g_k[BB * NN * SS];
__device__ __align__(16) float g_v[BB * NN * SS];
__device__ __align__(16) float g_slots[BB * KK * SS];
__device__ __align__(16) float g_q[BB * KK * SS];
__device__ __align__(16) float g_partial[BB * NBLK * PART];
__device__ __align__(16) float g_denom[BB * KK];

// ---------------- helpers ----------------
typedef unsigned long long ull;
__device__ __forceinline__ ull ffma2(ull a, ull b, ull c) {
    ull d;
    asm("fma.rn.f32x2 %0, %1, %2, %3;" : "=l"(d) : "l"(a), "l"(b), "l"(c));
    return d;
}
__device__ __forceinline__ float ull_lo(ull u) {
    return __uint_as_float((unsigned int)(u & 0xffffffffull));
}
__device__ __forceinline__ float ull_hi(ull u) {
    return __uint_as_float((unsigned int)(u >> 32));
}

__device__ __forceinline__ void mma16816(float& c0, float& c1, float& c2,
                                         float& c3, uint32_t a0, uint32_t a1,
                                         uint32_t a2, uint32_t a3, uint32_t b0,
                                         uint32_t b1) {
    asm volatile(
        "mma.sync.aligned.m16n8k16.row.col.f32.bf16.bf16.f32 "
        "{%0,%1,%2,%3}, {%4,%5,%6,%7}, {%8,%9}, {%0,%1,%2,%3};"
        : "+f"(c0), "+f"(c1), "+f"(c2), "+f"(c3)
        : "r"(a0), "r"(a1), "r"(a2), "r"(a3), "r"(b0), "r"(b1));
}
__device__ __forceinline__ void ldm4(uint32_t& r0, uint32_t& r1, uint32_t& r2,
                                     uint32_t& r3, uint32_t addr) {
    asm volatile(
        "ldmatrix.sync.aligned.m8n8.x4.shared.b16 {%0,%1,%2,%3}, [%4];"
        : "=r"(r0), "=r"(r1), "=r"(r2), "=r"(r3) : "r"(addr));
}
__device__ __forceinline__ ull pack_hi_lo(float a, float b, float c, float d,
                                          ull& lo_out) {
    __nv_bfloat162 h0 = __floats2bfloat162_rn(a, b);
    __nv_bfloat162 h1 = __floats2bfloat162_rn(c, d);
    __nv_bfloat162 l0 = __floats2bfloat162_rn(a - __low2float(h0), b - __high2float(h0));
    __nv_bfloat162 l1 = __floats2bfloat162_rn(c - __low2float(h1), d - __high2float(h1));
    lo_out = ((ull)(*(uint32_t*)&l1) << 32) | (*(uint32_t*)&l0);
    return ((ull)(*(uint32_t*)&h1) << 32) | (*(uint32_t*)&h0);
}
__device__ __forceinline__ uint32_t pack2(float a, float b, uint32_t& lo) {
    __nv_bfloat162 h = __floats2bfloat162_rn(a, b);
    __nv_bfloat162 l = __floats2bfloat162_rn(a - __low2float(h), b - __high2float(h));
    lo = *(uint32_t*)&l;
    return *(uint32_t*)&h;
}

// ---------------- Kernel A: two-pass LN + 4x K-split bf16 HMMA (R13) --------
#define RSTR 144
#define A_HI 0
#define A_LO (64 * RSTR)                 /* 9216 */
#define B_HI (2 * 64 * RSTR)             /* 18432 */
#define B_LO (B_HI + 32 * RSTR)          /* 23040 */
#define MURS (B_LO + 32 * RSTR)          /* 27648 */
#define SMEM_LN (MURS + 512)             /* 28160 */

__global__ void __launch_bounds__(256, 6) ln_proj_tc(
    const float* __restrict__ x, const float* __restrict__ lnw,
    const float* __restrict__ lnb, const float* __restrict__ wk,
    const float* __restrict__ wvm, const float* __restrict__ init_slots,
    const float* __restrict__ ln_s_w, const float* __restrict__ ln_s_b,
    const float* __restrict__ wq) {
    extern __shared__ char smem[];
    int tid = threadIdx.x, wid = tid >> 5, lane = tid & 31;
    int bx = blockIdx.x;

    // ---- fused q_init blocks ----
    if (bx >= NPROJ) {
        float* smq = (float*)smem;
        int b = bx - NPROJ;
        if (tid < 128) {
            int s = tid & 15;
            float v = init_slots[b * 128 + tid];
            float sum = v, sq = v * v;
#pragma unroll
            for (int o = 8; o; o >>= 1) {
                sum += __shfl_xor_sync(0xffffffffu, sum, o, 16);
                sq += __shfl_xor_sync(0xffffffffu, sq, o, 16);
            }
            float mu = sum * (1.f / SS);
            float rs = rsqrtf(sq * (1.f / SS) - mu * mu + 1e-5f);
            smq[tid] = (v - mu) * rs * ln_s_w[s] + ln_s_b[s];
        }
        __syncthreads();
        if (tid < 128) {
            int k = tid >> 4, t = tid & 15;
            float a = 0.f;
#pragma unroll
            for (int ss = 0; ss < SS; ss++) a += smq[k * SS + ss] * wq[t * SS + ss];
            g_q[b * 128 + tid] = a * 0.25f;
        }
        return;
    }

    uint32_t sb = (uint32_t)__cvta_generic_to_shared(smem);

    // ---- pass 1: row sums only ----
    {
        float s[8], q[8];
        const float4* xr = (const float4*)(x + ((size_t)bx * 64 + wid * 8) * DD);
#pragma unroll
        for (int rr = 0; rr < 8; rr++) {
            float4 a = xr[rr * 64 + lane];
            float4 c = xr[rr * 64 + lane + 32];
            s[rr] = ((a.x + a.y) + (a.z + a.w)) + ((c.x + c.y) + (c.z + c.w));
            q[rr] = ((a.x * a.x + a.y * a.y) + (a.z * a.z + a.w * a.w)) +
                    ((c.x * c.x + c.y * c.y) + (c.z * c.z + c.w * c.w));
        }
#pragma unroll
        for (int o = 16; o; o >>= 1) {
#pragma unroll
            for (int rr = 0; rr < 8; rr++) {
                s[rr] += __shfl_xor_sync(0xffffffffu, s[rr], o);
                q[rr] += __shfl_xor_sync(0xffffffffu, q[rr], o);
            }
        }
#pragma unroll
        for (int rr = 0; rr < 8; rr++) {
            if (lane == rr) {
                float mu = s[rr] * (1.f / DD);
                float rs = rsqrtf(q[rr] * (1.f / DD) - mu * mu + 1e-5f);
                *(float2*)(smem + MURS + (wid * 8 + rr) * 8) = make_float2(mu, rs);
            }
        }
    }

    int rtile = wid >> 1, chalf = wid & 1;
    float acc[2][4];
#pragma unroll
    for (int t = 0; t < 2; t++)
#pragma unroll
        for (int j = 0; j < 4; j++) acc[t][j] = 0.f;

#pragma unroll 1
    for (int h = 0; h < 4; h++) {
        __syncthreads();  // h=0: mu/rs ready; h>0: previous MMA reads done

        // ---- stage B K-quarter (L2-hot weights): 32 rows x 64 cols
        {
            int row = tid >> 3, seg = tid & 7;
            const float* src = ((row < SS) ? (wk + row * DD)
                                           : (wvm + (row - SS) * DD)) +
                               h * 64 + seg * 8;
            char* bh = smem + B_HI + row * RSTR + seg * 16;
            char* bl = smem + B_LO + row * RSTR + seg * 16;
#pragma unroll
            for (int i = 0; i < 2; i++) {
                float4 f = *(const float4*)(src + i * 4);
                ull lo;
                ull hi = pack_hi_lo(f.x, f.y, f.z, f.w, lo);
                *(ull*)(bh + i * 8) = hi;
                *(ull*)(bl + i * 8) = lo;
            }
        }

        // ---- stage A K-quarter: reload x (L2 hit), normalize, split
        {
            const float2* xr2 =
                (const float2*)(x + ((size_t)bx * 64 + wid * 8) * DD + h * 64);
            float2 w2 = ((const float2*)lnw)[h * 32 + lane];
            float2 b2 = ((const float2*)lnb)[h * 32 + lane];
#pragma unroll
            for (int rr = 0; rr < 8; rr++) {
                float2 a = xr2[rr * 128 + lane];
                float2 mr = *(const float2*)(smem + MURS + (wid * 8 + rr) * 8);
                float ox = (a.x - mr.x) * mr.y * w2.x + b2.x;
                float oy = (a.y - mr.x) * mr.y * w2.y + b2.y;
                uint32_t lo;
                uint32_t hi = pack2(ox, oy, lo);
                char* ah = smem + A_HI + (wid * 8 + rr) * RSTR + 4 * lane;
                *(uint32_t*)ah = hi;
                *(uint32_t*)(ah + (A_LO - A_HI)) = lo;
            }
        }
        __syncthreads();

        // ---- MMA: 4 k-steps, ldmatrix fragments
        {
            int tr = lane & 7, sel = lane >> 3;
            uint32_t a_addr = sb + A_HI +
                              (uint32_t)(rtile * 16 + tr + ((sel & 1) << 3)) * RSTR +
                              ((sel >> 1) << 4);
            uint32_t b_addr = sb + B_HI +
                              (uint32_t)(chalf * 16 + tr + ((sel >> 1) << 3)) * RSTR +
                              ((sel & 1) << 4);
#pragma unroll
            for (int ks = 0; ks < 4; ks++) {
                uint32_t ah0, ah1, ah2, ah3, al0, al1, al2, al3;
                uint32_t bh0, bh1, bh2, bh3, bl0, bl1, bl2, bl3;
                ldm4(ah0, ah1, ah2, ah3, a_addr + ks * 32);
                ldm4(al0, al1, al2, al3, a_addr + (A_LO - A_HI) + ks * 32);
                ldm4(bh0, bh1, bh2, bh3, b_addr + ks * 32);
                ldm4(bl0, bl1, bl2, bl3, b_addr + (B_LO - B_HI) + ks * 32);
                mma16816(acc[0][0], acc[0][1], acc[0][2], acc[0][3],
                         ah0, ah1, ah2, ah3, bh0, bh1);
                mma16816(acc[0][0], acc[0][1], acc[0][2], acc[0][3],
                         al0, al1, al2, al3, bh0, bh1);
                mma16816(acc[0][0], acc[0][1], acc[0][2], acc[0][3],
                         ah0, ah1, ah2, ah3, bl0, bl1);
                mma16816(acc[1][0], acc[1][1], acc[1][2], acc[1][3],
                         ah0, ah1, ah2, ah3, bh2, bh3);
                mma16816(acc[1][0], acc[1][1], acc[1][2], acc[1][3],
                         al0, al1, al2, al3, bh2, bh3);
                mma16816(acc[1][0], acc[1][1], acc[1][2], acc[1][3],
                         ah0, ah1, ah2, ah3, bl2, bl3);
            }
        }
    }

    // ---- epilogue
    {
        size_t row0 = (size_t)bx * 64 + rtile * 16 + (lane >> 2);
        int c0 = (lane & 3) * 2;
        float* dst = chalf ? g_v : g_k;
#pragma unroll
        for (int t = 0; t < 2; t++) {
            int col = t * 8 + c0;
            *(float2*)(dst + row0 * SS + col) = make_float2(acc[t][0], acc[t][1]);
            *(float2*)(dst + (row0 + 8) * SS + col) = make_float2(acc[t][2], acc[t][3]);
        }
    }
}

// ---------------- Kernel B: attention streaming pass (v2 tail) --------------
// Denominator computed in softmax phase via warp shfl-reduce; numerator tail
// maps exactly onto 256 threads = 8k x 8 f32x2-pairs x 4 n-quarters.
__global__ void __launch_bounds__(256) attn_kernel(float* __restrict__ out_attn,
                                                   int last) {
    __shared__ float sm_q[KK * SS];
    __shared__ ull sm_p2[KK * 257];          /* [k][n] padded */
    __shared__ float sm_v[NCHUNK * 18];
    __shared__ float2 sm_r[256];
    __shared__ float sm_dp[8 * KK];          /* per-warp denom partials */
    int tid = threadIdx.x, wid = tid >> 5;
    int b = blockIdx.y, nb = blockIdx.x;
    size_t nrow = (size_t)b * NN + (size_t)nb * NCHUNK + tid;

    // stage v to smem (cooperative), q to smem, k row to regs
    {
        const ull* vs =
            (const ull*)(g_v + ((size_t)b * NN + (size_t)nb * NCHUNK) * SS);
#pragma unroll
        for (int i = tid; i < NCHUNK * 8; i += 256) {
            int n = i >> 3, j = i & 7;
            *(ull*)&sm_v[n * 18 + 2 * j] = vs[i];
        }
    }
    union { float4 f4[4]; ull u[8]; } kf;
    {
        const float4* kf4 = (const float4*)(g_k + nrow * SS);
#pragma unroll
        for (int j = 0; j < 4; j++) kf.f4[j] = kf4[j];
    }
    if (tid < 32) ((float4*)sm_q)[tid] = ((const float4*)(g_q + b * 128))[tid];
    __syncthreads();

    {
        const float4* q4 = (const float4*)sm_q;
        float lg[KK];
#pragma unroll
        for (int kk = 0; kk < KK; kk++) {
            union { float4 f; ull u[2]; } qa, qb, qc, qd;
            qa.f = q4[kk * 4 + 0];
            qb.f = q4[kk * 4 + 1];
            qc.f = q4[kk * 4 + 2];
            qd.f = q4[kk * 4 + 3];
            ull a0 = ffma2(qa.u[0], kf.u[0], 0ull);
            ull a1 = ffma2(qa.u[1], kf.u[1], 0ull);
            a0 = ffma2(qb.u[0], kf.u[2], a0);
            a1 = ffma2(qb.u[1], kf.u[3], a1);
            a0 = ffma2(qc.u[0], kf.u[4], a0);
            a1 = ffma2(qc.u[1], kf.u[5], a1);
            a0 = ffma2(qd.u[0], kf.u[6], a0);
            a1 = ffma2(qd.u[1], kf.u[7], a1);
            lg[kk] = (ull_lo(a0) + ull_hi(a0)) + (ull_lo(a1) + ull_hi(a1));
        }
        float m = lg[0];
#pragma unroll
        for (int kk = 1; kk < KK; kk++) m = fmaxf(m, lg[kk]);
        float sum = 0.f;
#pragma unroll
        for (int kk = 0; kk < KK; kk++) {
            lg[kk] = __expf(lg[kk] - m);
            sum += lg[kk];
        }
        float inv = 1.f / sum;
#pragma unroll
        for (int kk = 0; kk < KK; kk++) {
            float p = lg[kk] * inv + 1e-8f;
            lg[kk] = p;
            unsigned int pb = __float_as_uint(p);
            sm_p2[kk * 257 + tid] = ((ull)pb << 32) | pb;
            if (last) out_attn[((size_t)(b * KK + kk)) * NN + nb * NCHUNK + tid] = p;
        }
        // per-warp denominator partials (full-warp reduce of each lg[kk])
#pragma unroll
        for (int o = 16; o; o >>= 1) {
#pragma unroll
            for (int kk = 0; kk < KK; kk++)
                lg[kk] += __shfl_xor_sync(0xffffffffu, lg[kk], o);
        }
        if ((tid & 31) == 0) {
#pragma unroll
            for (int kk = 0; kk < KK; kk++) sm_dp[wid * KK + kk] = lg[kk];
        }
    }
    __syncthreads();

    // numerator: thread = (quarter, k, cpair); 64 n-iterations each
    {
        int quarter = tid >> 6, k = (tid >> 3) & 7, cp = tid & 7;
        const ull* prow = sm_p2 + k * 257;
        ull a0 = 0ull, a1 = 0ull, a2 = 0ull, a3 = 0ull;
        int n0 = quarter * 64;
#pragma unroll 2
        for (int n = n0; n < n0 + 64; n += 4) {
            a0 = ffma2(prow[n], *(const ull*)&sm_v[n * 18 + 2 * cp], a0);
            a1 = ffma2(prow[n + 1], *(const ull*)&sm_v[(n + 1) * 18 + 2 * cp], a1);
            a2 = ffma2(prow[n + 2], *(const ull*)&sm_v[(n + 2) * 18 + 2 * cp], a2);
            a3 = ffma2(prow[n + 3], *(const ull*)&sm_v[(n + 3) * 18 + 2 * cp], a3);
        }
        sm_r[tid] = make_float2((ull_lo(a0) + ull_lo(a1)) + (ull_lo(a2) + ull_lo(a3)),
                                (ull_hi(a0) + ull_hi(a1)) + (ull_hi(a2) + ull_hi(a3)));
    }
    __syncthreads();

    // combine quarters + denom, write partials
    {
        float* gp = g_partial + ((size_t)b * NBLK + nb) * PART;
        if (tid < 64) {
            int k = tid >> 3, cp = tid & 7;
            float2 A = sm_r[tid], B = sm_r[tid + 64];
            float2 C = sm_r[tid + 128], D = sm_r[tid + 192];
            gp[k * SS + 2 * cp] = (A.x + B.x) + (C.x + D.x);
            gp[k * SS + 2 * cp + 1] = (A.y + B.y) + (C.y + D.y);
        } else if (tid < 72) {
            int k = tid - 64;
            float d = 0.f;
#pragma unroll
            for (int w = 0; w < 8; w++) d += sm_dp[w * KK + k];
            gp[128 + k] = d;
        }
    }
}

// ---------------- Kernel C: per-(b,k) reduce + GRU + LN + MLP + next-q ------
__global__ void __launch_bounds__(128) update_kernel(
    const float* __restrict__ init_slots, const float* __restrict__ w_ih,
    const float* __restrict__ w_hh, const float* __restrict__ b_ih,
    const float* __restrict__ b_hh, const float* __restrict__ ln_m_w,
    const float* __restrict__ ln_m_b, const float* __restrict__ mlp_w1,
    const float* __restrict__ mlp_b1, const float* __restrict__ mlp_w2,
    const float* __restrict__ mlp_b2, const float* __restrict__ ln_s_w,
    const float* __restrict__ ln_s_b, const float* __restrict__ wq,
    float* __restrict__ out_slots, int iter, int last) {
    __shared__ float s_num[16], s_upd[16], s_hp[16], s_h[16], s_y[16];
    __shared__ float s_h1[128], s_ns[16];
    __shared__ float s_den;
    int t = threadIdx.x;
    int b = blockIdx.x >> 3, k = blockIdx.x & 7;
    const float* slots_in =
        (iter == 0) ? (init_slots + b * 128) : (g_slots + b * 128);

    if (t < 17) {
        float s = 0.f;
        int off = (t < 16) ? (k * SS + t) : (128 + k);
#pragma unroll
        for (int j = 0; j < NBLK; j++)
            s += g_partial[((size_t)(b * NBLK + j)) * PART + off];
        if (t < 16) s_num[t] = s;
        else { s_den = s; g_denom[b * KK + k] = s; }
    }
    if (t < 16) s_hp[t] = slots_in[k * SS + t];
    __syncthreads();
    if (t < 16) s_upd[t] = s_num[t] / s_den;
    __syncthreads();

    // GRU (torch gate order [r,z,n])
    if (t < 16) {
        float ir = b_ih[t], iz = b_ih[SS + t], inn = b_ih[2 * SS + t];
        float hr = b_hh[t], hz = b_hh[SS + t], hn = b_hh[2 * SS + t];
#pragma unroll
        for (int tt = 0; tt < SS; tt++) {
            float u = s_upd[tt], hp = s_hp[tt];
            ir += w_ih[t * SS + tt] * u;
            iz += w_ih[(SS + t) * SS + tt] * u;
            inn += w_ih[(2 * SS + t) * SS + tt] * u;
            hr += w_hh[t * SS + tt] * hp;
            hz += w_hh[(SS + t) * SS + tt] * hp;
            hn += w_hh[(2 * SS + t) * SS + tt] * hp;
        }
        float r = 1.f / (1.f + __expf(-(ir + hr)));
        float z = 1.f / (1.f + __expf(-(iz + hz)));
        float n = tanhf(inn + r * hn);
        float h = (1.f - z) * n + z * s_hp[t];
        s_h[t] = h;
        float sum = h, sq = h * h;
#pragma unroll
        for (int o = 8; o; o >>= 1) {
            sum += __shfl_xor_sync(0xffffu, sum, o, 16);
            sq += __shfl_xor_sync(0xffffu, sq, o, 16);
        }
        float mu = sum * (1.f / SS);
        float rs = rsqrtf(sq * (1.f / SS) - mu * mu + 1e-5f);
        s_y[t] = (h - mu) * rs * ln_m_w[t] + ln_m_b[t];
    }
    __syncthreads();

    // MLP1: one hidden unit per thread
    {
        float a = mlp_b1[t];
#pragma unroll
        for (int s = 0; s < SS; s++) a += mlp_w1[t * SS + s] * s_y[s];
        s_h1[t] = fmaxf(a, 0.f);
    }
    __syncthreads();

    // MLP2: 16 outputs x 8 threads, width-8 shfl reduce
    {
        int s = t >> 3, part = t & 7;
        float a = 0.f;
#pragma unroll
        for (int j = 0; j < 16; j++)
            a += mlp_w2[s * HH + part * 16 + j] * s_h1[part * 16 + j];
        a += __shfl_xor_sync(0xffffffffu, a, 4, 8);
        a += __shfl_xor_sync(0xffffffffu, a, 2, 8);
        a += __shfl_xor_sync(0xffffffffu, a, 1, 8);
        if (part == 0) {
            float ns = s_h[s] + mlp_b2[s] + a;
            s_ns[s] = ns;
            g_slots[b * 128 + k * SS + s] = ns;
            if (last) out_slots[b * 128 + k * SS + s] = ns;
        }
    }
    __syncthreads();

    if (!last && t < 16) {
        float v = s_ns[t];
        float sum = v, sq = v * v;
#pragma unroll
        for (int o = 8; o; o >>= 1) {
            sum += __shfl_xor_sync(0xffffu, sum, o, 16);
            sq += __shfl_xor_sync(0xffffu, sq, o, 16);
        }
        float mu = sum * (1.f / SS);
        float rs = rsqrtf(sq * (1.f / SS) - mu * mu + 1e-5f);
        s_y[t] = (v - mu) * rs * ln_s_w[t] + ln_s_b[t];
        __syncwarp(0xffffu);
        float a = 0.f;
#pragma unroll
        for (int s = 0; s < SS; s++) a += s_y[s] * wq[t * SS + s];
        g_q[b * 128 + k * SS + t] = a * 0.25f;
    }
}

// ---------------- Kernel D: normalize emitted attention (float4) ------------
__global__ void __launch_bounds__(256) norm_attn_kernel(float4* __restrict__ out_attn) {
    int i = blockIdx.x * 256 + threadIdx.x;
    float4 p = out_attn[i];
    float inv = 1.f / g_denom[i >> 10];
    p.x *= inv; p.y *= inv; p.z *= inv; p.w *= inv;
    out_attn[i] = p;
}

// ---------------- launch ----------------
extern "C" void kernel_launch(void* const* d_in, const int* in_sizes, int n_in,
                              void* d_out, int out_size) {
    (void)in_sizes; (void)n_in; (void)out_size;
    const float* inputs     = (const float*)d_in[0];
    const float* init_slots = (const float*)d_in[1];
    const float* ln_in_w    = (const float*)d_in[2];
    const float* ln_in_b    = (const float*)d_in[3];
    const float* ln_s_w     = (const float*)d_in[4];
    const float* ln_s_b     = (const float*)d_in[5];
    const float* ln_m_w     = (const float*)d_in[6];
    const float* ln_m_b     = (const float*)d_in[7];
    const float* wq         = (const float*)d_in[8];
    const float* wk         = (const float*)d_in[9];
    const float* wv         = (const float*)d_in[10];
    const float* w_ih       = (const float*)d_in[11];
    const float* w_hh       = (const float*)d_in[12];
    const float* b_ih       = (const float*)d_in[13];
    const float* b_hh       = (const float*)d_in[14];
    const float* mlp_w1     = (const float*)d_in[15];
    const float* mlp_b1     = (const float*)d_in[16];
    const float* mlp_w2     = (const float*)d_in[17];
    const float* mlp_b2     = (const float*)d_in[18];
    float* out = (float*)d_out;
    float* out_slots = out;
    float* out_attn = out + BB * KK * SS;

    cudaFuncSetAttribute(ln_proj_tc, cudaFuncAttributeMaxDynamicSharedMemorySize,
                         SMEM_LN);
    ln_proj_tc<<<NTOT, 256, SMEM_LN>>>(inputs, ln_in_w, ln_in_b, wk, wv,
                                       init_slots, ln_s_w, ln_s_b, wq);
    for (int it = 0; it < 3; it++) {
        int last = (it == 2) ? 1 : 0;
        dim3 gb(NBLK, BB);
        attn_kernel<<<gb, 256>>>(out_attn, last);
        update_kernel<<<BB * KK, 128>>>(init_slots, w_ih, w_hh, b_ih, b_hh,
                                        ln_m_w, ln_m_b, mlp_w1, mlp_b1, mlp_w2,
                                        mlp_b2, ln_s_w, ln_s_b, wq, out_slots,
                                        it, last);
    }
    norm_attn_kernel<<<(BB * KK * NN) / 1024, 256>>>((float4*)out_attn);
}